// round 4
// baseline (speedup 1.0000x reference)
#include <cuda_runtime.h>
#include <cuda_bf16.h>
#include <math.h>
#include <stdint.h>

#define T_TOK 4096
#define DIM   1024
#define NEXP  8
#define HID   2816
#define NSLOT (T_TOK*2)

typedef unsigned long long ull;

// ---------------- device scratch (static, no allocs) ----------------
__device__ __align__(16) __nv_bfloat16 g_W1h[(size_t)NEXP*HID*DIM];
__device__ __align__(16) __nv_bfloat16 g_W1l[(size_t)NEXP*HID*DIM];
__device__ __align__(16) __nv_bfloat16 g_W2h[(size_t)NEXP*HID*DIM];
__device__ __align__(16) __nv_bfloat16 g_W2l[(size_t)NEXP*HID*DIM];
__device__ __align__(16) __nv_bfloat16 g_W3h[(size_t)NEXP*DIM*HID];
__device__ __align__(16) __nv_bfloat16 g_W3l[(size_t)NEXP*DIM*HID];
__device__ __align__(16) __nv_bfloat16 g_xh[(size_t)T_TOK*DIM];
__device__ __align__(16) __nv_bfloat16 g_xl[(size_t)T_TOK*DIM];
__device__ __align__(16) __nv_bfloat16 g_Hh[(size_t)NSLOT*HID];
__device__ __align__(16) __nv_bfloat16 g_Hl[(size_t)NSLOT*HID];
__device__ int   g_tok[NSLOT];
__device__ float g_wslot[NSLOT];
__device__ int   g_te[NSLOT];
__device__ float g_tw[NSLOT];
__device__ int   g_cnt[NEXP];
__device__ int   g_off[NEXP + 1];
__device__ int   g_cur[NEXP];

// ---------------- helpers ----------------
__device__ __forceinline__ uint32_t s2u(const void* p) {
    uint32_t a;
    asm("{ .reg .u64 t; cvta.to.shared.u64 t, %1; cvt.u32.u64 %0, t; }" : "=r"(a) : "l"(p));
    return a;
}
__device__ __forceinline__ unsigned bfpack(float lo_elem, float hi_elem) {
    unsigned r;
    asm("cvt.rn.bf16x2.f32 %0, %1, %2;" : "=r"(r) : "f"(hi_elem), "f"(lo_elem));
    return r;
}
__device__ __forceinline__ void split4(float4 v, ull& h, ull& l) {
    unsigned h0 = bfpack(v.x, v.y);
    unsigned h1 = bfpack(v.z, v.w);
    float f0 = __uint_as_float(h0 << 16);
    float f1 = __uint_as_float(h0 & 0xffff0000u);
    float f2 = __uint_as_float(h1 << 16);
    float f3 = __uint_as_float(h1 & 0xffff0000u);
    unsigned l0 = bfpack(v.x - f0, v.y - f1);
    unsigned l1 = bfpack(v.z - f2, v.w - f3);
    h = (ull)h0 | ((ull)h1 << 32);
    l = (ull)l0 | ((ull)l1 << 32);
}
__device__ __forceinline__ void ldm4(uint32_t& r0, uint32_t& r1, uint32_t& r2, uint32_t& r3, uint32_t a) {
    asm volatile("ldmatrix.sync.aligned.m8n8.x4.shared.b16 {%0,%1,%2,%3}, [%4];"
        : "=r"(r0), "=r"(r1), "=r"(r2), "=r"(r3) : "r"(a));
}
__device__ __forceinline__ void mma16816(float* c, const uint32_t* a, const uint32_t* b) {
    asm volatile("mma.sync.aligned.m16n8k16.row.col.f32.bf16.bf16.f32 "
        "{%0,%1,%2,%3}, {%4,%5,%6,%7}, {%8,%9}, {%0,%1,%2,%3};"
        : "+f"(c[0]), "+f"(c[1]), "+f"(c[2]), "+f"(c[3])
        : "r"(a[0]), "r"(a[1]), "r"(a[2]), "r"(a[3]), "r"(b[0]), "r"(b[1]));
}
__device__ __forceinline__ void cpa16(uint32_t dst, const void* src) {
    asm volatile("cp.async.cg.shared.global [%0], [%1], 16;" :: "r"(dst), "l"(src) : "memory");
}
#define CP_COMMIT() asm volatile("cp.async.commit_group;" ::: "memory")
#define CP_WAIT2()  asm volatile("cp.async.wait_group 2;" ::: "memory")

// smem geometry: rows padded to 40 halves (k32 + 8 pad), conflict-free ldmatrix
#define ROWP  40
#define SSTR1 20480   // halves/stage GEMM1: Ah(5120) Al B1h(2560) B1l B2h B2l
#define SSTR2 15360   // halves/stage GEMM2: Ah(5120) Al Bh(2560) Bl
#define NSTG  4
#define SMEM1 (NSTG*SSTR1*2)
#define SMEM2 (NSTG*SSTR2*2)

// ---------------- K: pre-split weights/x to planar bf16 hi/lo + zero out/cnt ----------------
__global__ void k_split(const float4* __restrict__ W1, const float4* __restrict__ W2,
                        const float4* __restrict__ W3, const float4* __restrict__ x,
                        float4* __restrict__ out) {
    const size_t n1 = (size_t)NEXP * HID * DIM / 4;   // per weight matrix, float4 units
    const size_t nx = (size_t)T_TOK * DIM / 4;
    const size_t total = 3 * n1 + 2 * nx;
    size_t t0 = (size_t)blockIdx.x * blockDim.x + threadIdx.x;
    if (t0 < NEXP) g_cnt[t0] = 0;
    size_t stride = (size_t)gridDim.x * blockDim.x;
    for (size_t i = t0; i < total; i += stride) {
        if (i < n1) {
            float4 v = W1[i]; ull h, l; split4(v, h, l);
            *(ull*)(g_W1h + i * 4) = h; *(ull*)(g_W1l + i * 4) = l;
        } else if (i < 2 * n1) {
            size_t j = i - n1;
            float4 v = W2[j]; ull h, l; split4(v, h, l);
            *(ull*)(g_W2h + j * 4) = h; *(ull*)(g_W2l + j * 4) = l;
        } else if (i < 3 * n1) {
            size_t j = i - 2 * n1;
            float4 v = W3[j]; ull h, l; split4(v, h, l);
            *(ull*)(g_W3h + j * 4) = h; *(ull*)(g_W3l + j * 4) = l;
        } else if (i < 3 * n1 + nx) {
            size_t j = i - 3 * n1;
            float4 v = x[j]; ull h, l; split4(v, h, l);
            *(ull*)(g_xh + j * 4) = h; *(ull*)(g_xl + j * 4) = l;
        } else {
            out[i - 3 * n1 - nx] = make_float4(0.f, 0.f, 0.f, 0.f);
        }
    }
}

// ---------------- gating ----------------
__global__ void k_gate(const float* __restrict__ x, const float* __restrict__ Wg) {
    int t = (blockIdx.x * blockDim.x + threadIdx.x) >> 5;
    int lane = threadIdx.x & 31;
    if (t >= T_TOK) return;
    const float4* xr = reinterpret_cast<const float4*>(x + (size_t)t * DIM);
    float s[NEXP];
#pragma unroll
    for (int e = 0; e < NEXP; e++) s[e] = 0.f;
    for (int i = lane; i < DIM / 4; i += 32) {
        float4 xv = xr[i];
#pragma unroll
        for (int e = 0; e < NEXP; e++) {
            float4 wv = reinterpret_cast<const float4*>(Wg + (size_t)e * DIM)[i];
            s[e] += xv.x * wv.x + xv.y * wv.y + xv.z * wv.z + xv.w * wv.w;
        }
    }
#pragma unroll
    for (int e = 0; e < NEXP; e++) {
#pragma unroll
        for (int o = 16; o > 0; o >>= 1) s[e] += __shfl_xor_sync(0xffffffffu, s[e], o);
    }
    if (lane == 0) {
        int b0 = 0; float v0 = s[0];
#pragma unroll
        for (int e = 1; e < NEXP; e++) if (s[e] > v0) { v0 = s[e]; b0 = e; }
        int b1 = -1; float v1 = -3.4e38f;
#pragma unroll
        for (int e = 0; e < NEXP; e++) if (e != b0 && s[e] > v1) { v1 = s[e]; b1 = e; }
        g_te[t * 2 + 0] = b0;  g_te[t * 2 + 1] = b1;
        g_tw[t * 2 + 0] = v0;  g_tw[t * 2 + 1] = v1;
        atomicAdd(&g_cnt[b0], 1);
        atomicAdd(&g_cnt[b1], 1);
    }
}

__global__ void k_scan() {
    int o = 0;
    for (int e = 0; e < NEXP; e++) { g_off[e] = o; g_cur[e] = o; o += g_cnt[e]; }
    g_off[NEXP] = o;
}

__global__ void k_assign() {
    int t = blockIdx.x * blockDim.x + threadIdx.x;
    if (t >= T_TOK) return;
#pragma unroll
    for (int k = 0; k < 2; k++) {
        int e = g_te[t * 2 + k];
        int pos = atomicAdd(&g_cur[e], 1);
        g_tok[pos] = t;
        g_wslot[pos] = g_tw[t * 2 + k];
    }
}

// ---------------- GEMM1 compute (one k32 chunk), unchanged layout ----------------
__device__ __forceinline__ void comp1(uint32_t smb, int sb, int wid, int lane,
                                      float (&A1)[2][4][4], float (&A2)[2][4][4]) {
#pragma unroll
    for (int ks = 0; ks < 2; ks++) {
        uint32_t ah[2][4], al[2][4];
#pragma unroll
        for (int mt = 0; mt < 2; mt++) {
            int row = (wid & 3) * 32 + mt * 16 + (lane & 15);
            int hc = ks * 16 + ((lane & 16) >> 1);
            uint32_t ad = smb + (uint32_t)(sb + row * ROWP + hc) * 2;
            ldm4(ah[mt][0], ah[mt][1], ah[mt][2], ah[mt][3], ad);
            ldm4(al[mt][0], al[mt][1], al[mt][2], al[mt][3], ad + 5120 * 2);
        }
        uint32_t b1h[4][2], b1l[4][2], b2h[4][2], b2l[4][2];
#pragma unroll
        for (int p = 0; p < 2; p++) {
            int nr = (wid >> 2) * 32 + p * 16 + (lane & 7) + ((lane & 16) >> 1);
            int hc = ks * 16 + (lane & 8);
            uint32_t bd = smb + (uint32_t)(sb + 10240 + nr * ROWP + hc) * 2;
            ldm4(b1h[2*p][0], b1h[2*p][1], b1h[2*p+1][0], b1h[2*p+1][1], bd);
            ldm4(b1l[2*p][0], b1l[2*p][1], b1l[2*p+1][0], b1l[2*p+1][1], bd + 2560 * 2);
            ldm4(b2h[2*p][0], b2h[2*p][1], b2h[2*p+1][0], b2h[2*p+1][1], bd + 5120 * 2);
            ldm4(b2l[2*p][0], b2l[2*p][1], b2l[2*p+1][0], b2l[2*p+1][1], bd + 7680 * 2);
        }
#pragma unroll
        for (int mt = 0; mt < 2; mt++)
#pragma unroll
            for (int nt = 0; nt < 4; nt++) {
                mma16816(A1[mt][nt], ah[mt], b1h[nt]);
                mma16816(A1[mt][nt], ah[mt], b1l[nt]);
                mma16816(A1[mt][nt], al[mt], b1h[nt]);
                mma16816(A2[mt][nt], ah[mt], b2h[nt]);
                mma16816(A2[mt][nt], ah[mt], b2l[nt]);
                mma16816(A2[mt][nt], al[mt], b2h[nt]);
            }
    }
}

// issue one stage of GEMM1 via cp.async (8 x 16B per thread)
__device__ __forceinline__ void issue1(uint32_t smb, int soff, int tid, const int* s_tok,
        const __nv_bfloat16* __restrict__ w1h, const __nv_bfloat16* __restrict__ w1l,
        const __nv_bfloat16* __restrict__ w2h, const __nv_bfloat16* __restrict__ w2l,
        int k0) {
#pragma unroll
    for (int i = 0; i < 2; i++) {
        int op = tid + (i << 8); int r = op >> 2, g = op & 3;
        size_t so = (size_t)s_tok[r] * DIM + k0 + g * 8;
        uint32_t d = smb + (uint32_t)(soff + r * ROWP + g * 8) * 2;
        cpa16(d, g_xh + so);
        cpa16(d + 5120 * 2, g_xl + so);
    }
    {
        int r = tid >> 2, g = tid & 3;
        size_t so = (size_t)r * DIM + k0 + g * 8;
        uint32_t d = smb + (uint32_t)(soff + 10240 + r * ROWP + g * 8) * 2;
        cpa16(d, w1h + so);
        cpa16(d + 2560 * 2, w1l + so);
        cpa16(d + 5120 * 2, w2h + so);
        cpa16(d + 7680 * 2, w2l + so);
    }
}

// ---------------- GEMM1: H = silu(X@W1^T)*(X@W2^T) ----------------
__global__ void __launch_bounds__(256, 1) k_ffn1() {
    int e = blockIdx.z;
    int rbeg = g_off[e], rend = g_off[e + 1];
    int row0 = rbeg + blockIdx.y * 128;
    if (row0 >= rend) return;
    int n0 = blockIdx.x * 64;

    extern __shared__ __align__(16) uint16_t sm16[];
    __shared__ int s_tok[128];
    int tid = threadIdx.x, wid = tid >> 5, lane = tid & 31;
    uint32_t smb = s2u(sm16);

    if (tid < 128) {
        int rr = row0 + tid;
        s_tok[tid] = g_tok[rr < rend ? rr : rbeg];
    }
    __syncthreads();

    const __nv_bfloat16* w1h = g_W1h + ((size_t)e * HID + n0) * DIM;
    const __nv_bfloat16* w1l = g_W1l + ((size_t)e * HID + n0) * DIM;
    const __nv_bfloat16* w2h = g_W2h + ((size_t)e * HID + n0) * DIM;
    const __nv_bfloat16* w2l = g_W2l + ((size_t)e * HID + n0) * DIM;

    float acc1[2][4][4], acc2[2][4][4];
#pragma unroll
    for (int a = 0; a < 2; a++)
#pragma unroll
        for (int b = 0; b < 4; b++)
#pragma unroll
            for (int c = 0; c < 4; c++) { acc1[a][b][c] = 0.f; acc2[a][b][c] = 0.f; }

    const int NC = DIM / 32;  // 32
#pragma unroll
    for (int s = 0; s < NSTG - 1; s++) {
        issue1(smb, s * SSTR1, tid, s_tok, w1h, w1l, w2h, w2l, s * 32);
        CP_COMMIT();
    }

    for (int c = 0; c < NC; c++) {
        int sb = (c & (NSTG - 1)) * SSTR1;
        CP_WAIT2();
        __syncthreads();
        if (c + NSTG - 1 < NC)
            issue1(smb, ((c + NSTG - 1) & (NSTG - 1)) * SSTR1, tid, s_tok,
                   w1h, w1l, w2h, w2l, (c + NSTG - 1) * 32);
        CP_COMMIT();
        comp1(smb, sb, wid, lane, acc1, acc2);
    }

    // epilogue: silu(g)*u, split, store planar H
    int wm = wid & 3, wn = wid >> 2;
#pragma unroll
    for (int mt = 0; mt < 2; mt++) {
        int rbse = row0 + wm * 32 + mt * 16 + (lane >> 2);
#pragma unroll
        for (int h2 = 0; h2 < 2; h2++) {
            int row = rbse + h2 * 8;
            if (row >= rend) continue;
            int colb = n0 + wn * 32 + (lane & 3) * 2;
            __nv_bfloat16* hh = g_Hh + (size_t)row * HID + colb;
            __nv_bfloat16* hl = g_Hl + (size_t)row * HID + colb;
#pragma unroll
            for (int nt = 0; nt < 4; nt++) {
                float g0 = acc1[mt][nt][h2 * 2 + 0], u0 = acc2[mt][nt][h2 * 2 + 0];
                float g1 = acc1[mt][nt][h2 * 2 + 1], u1 = acc2[mt][nt][h2 * 2 + 1];
                float hv0 = g0 * u0 / (1.f + expf(-g0));
                float hv1 = g1 * u1 / (1.f + expf(-g1));
                __nv_bfloat16 a0 = __float2bfloat16(hv0);
                __nv_bfloat16 a1 = __float2bfloat16(hv1);
                __nv_bfloat16 b0 = __float2bfloat16(hv0 - __bfloat162float(a0));
                __nv_bfloat16 b1 = __float2bfloat16(hv1 - __bfloat162float(a1));
                __nv_bfloat162 ph; ph.x = a0; ph.y = a1;
                __nv_bfloat162 pl; pl.x = b0; pl.y = b1;
                *(__nv_bfloat162*)(hh + nt * 8) = ph;
                *(__nv_bfloat162*)(hl + nt * 8) = pl;
            }
        }
    }
}

// ---------------- GEMM2 compute ----------------
__device__ __forceinline__ void comp2(uint32_t smb, int sb, int wid, int lane,
                                      float (&A)[2][4][4]) {
#pragma unroll
    for (int ks = 0; ks < 2; ks++) {
        uint32_t ah[2][4], al[2][4];
#pragma unroll
        for (int mt = 0; mt < 2; mt++) {
            int row = (wid & 3) * 32 + mt * 16 + (lane & 15);
            int hc = ks * 16 + ((lane & 16) >> 1);
            uint32_t ad = smb + (uint32_t)(sb + row * ROWP + hc) * 2;
            ldm4(ah[mt][0], ah[mt][1], ah[mt][2], ah[mt][3], ad);
            ldm4(al[mt][0], al[mt][1], al[mt][2], al[mt][3], ad + 5120 * 2);
        }
        uint32_t bh[4][2], bl[4][2];
#pragma unroll
        for (int p = 0; p < 2; p++) {
            int nr = (wid >> 2) * 32 + p * 16 + (lane & 7) + ((lane & 16) >> 1);
            int hc = ks * 16 + (lane & 8);
            uint32_t bd = smb + (uint32_t)(sb + 10240 + nr * ROWP + hc) * 2;
            ldm4(bh[2*p][0], bh[2*p][1], bh[2*p+1][0], bh[2*p+1][1], bd);
            ldm4(bl[2*p][0], bl[2*p][1], bl[2*p+1][0], bl[2*p+1][1], bd + 2560 * 2);
        }
#pragma unroll
        for (int mt = 0; mt < 2; mt++)
#pragma unroll
            for (int nt = 0; nt < 4; nt++) {
                mma16816(A[mt][nt], ah[mt], bh[nt]);
                mma16816(A[mt][nt], ah[mt], bl[nt]);
                mma16816(A[mt][nt], al[mt], bh[nt]);
            }
    }
}

// issue one stage of GEMM2 (6 x 16B per thread)
__device__ __forceinline__ void issue2(uint32_t smb, int soff, int tid, const int* s_row,
        const __nv_bfloat16* __restrict__ w3h, const __nv_bfloat16* __restrict__ w3l,
        int k0) {
#pragma unroll
    for (int i = 0; i < 2; i++) {
        int op = tid + (i << 8); int r = op >> 2, g = op & 3;
        size_t so = (size_t)s_row[r] * HID + k0 + g * 8;
        uint32_t d = smb + (uint32_t)(soff + r * ROWP + g * 8) * 2;
        cpa16(d, g_Hh + so);
        cpa16(d + 5120 * 2, g_Hl + so);
    }
    {
        int r = tid >> 2, g = tid & 3;
        size_t so = (size_t)r * HID + k0 + g * 8;
        uint32_t d = smb + (uint32_t)(soff + 10240 + r * ROWP + g * 8) * 2;
        cpa16(d, w3h + so);
        cpa16(d + 2560 * 2, w3l + so);
    }
}

// ---------------- GEMM2: out[tok] += w * (H @ W3^T) ----------------
__global__ void __launch_bounds__(256, 1) k_ffn2(float* __restrict__ out) {
    int e = blockIdx.z;
    int rbeg = g_off[e], rend = g_off[e + 1];
    int row0 = rbeg + blockIdx.y * 128;
    if (row0 >= rend) return;
    int n0 = blockIdx.x * 64;

    extern __shared__ __align__(16) uint16_t sm16[];
    __shared__ int s_row[128];
    int tid = threadIdx.x, wid = tid >> 5, lane = tid & 31;
    uint32_t smb = s2u(sm16);

    if (tid < 128) {
        int rr = row0 + tid;
        s_row[tid] = (rr < rend) ? rr : rbeg;
    }
    __syncthreads();

    const __nv_bfloat16* w3h = g_W3h + ((size_t)e * DIM + n0) * HID;
    const __nv_bfloat16* w3l = g_W3l + ((size_t)e * DIM + n0) * HID;

    float acc[2][4][4];
#pragma unroll
    for (int a = 0; a < 2; a++)
#pragma unroll
        for (int b = 0; b < 4; b++)
#pragma unroll
            for (int c = 0; c < 4; c++) acc[a][b][c] = 0.f;

    const int NC = HID / 32;  // 88
#pragma unroll
    for (int s = 0; s < NSTG - 1; s++) {
        issue2(smb, s * SSTR2, tid, s_row, w3h, w3l, s * 32);
        CP_COMMIT();
    }

    for (int c = 0; c < NC; c++) {
        int sb = (c & (NSTG - 1)) * SSTR2;
        CP_WAIT2();
        __syncthreads();
        if (c + NSTG - 1 < NC)
            issue2(smb, ((c + NSTG - 1) & (NSTG - 1)) * SSTR2, tid, s_row,
                   w3h, w3l, (c + NSTG - 1) * 32);
        CP_COMMIT();
        comp2(smb, sb, wid, lane, acc);
    }

    // epilogue: scale by gate weight, atomicAdd into out
    int wm = wid & 3, wn = wid >> 2;
#pragma unroll
    for (int mt = 0; mt < 2; mt++) {
        int rbse = row0 + wm * 32 + mt * 16 + (lane >> 2);
#pragma unroll
        for (int h2 = 0; h2 < 2; h2++) {
            int slot = rbse + h2 * 8;
            if (slot >= rend) continue;
            int tk = g_tok[slot];
            float wv = g_wslot[slot];
            float* ob = out + (size_t)tk * DIM + n0 + wn * 32 + (lane & 3) * 2;
#pragma unroll
            for (int nt = 0; nt < 4; nt++) {
                atomicAdd(ob + nt * 8,     acc[mt][nt][h2 * 2 + 0] * wv);
                atomicAdd(ob + nt * 8 + 1, acc[mt][nt][h2 * 2 + 1] * wv);
            }
        }
    }
}

// ---------------- launch ----------------
extern "C" void kernel_launch(void* const* d_in, const int* in_sizes, int n_in,
                              void* d_out, int out_size) {
    const float* x  = (const float*)d_in[0];
    const float* Wg = (const float*)d_in[1];
    const float* W1 = (const float*)d_in[2];
    const float* W2 = (const float*)d_in[3];
    const float* W3 = (const float*)d_in[4];
    float* out = (float*)d_out;

    cudaFuncSetAttribute(k_ffn1, cudaFuncAttributeMaxDynamicSharedMemorySize, SMEM1);
    cudaFuncSetAttribute(k_ffn2, cudaFuncAttributeMaxDynamicSharedMemorySize, SMEM2);

    k_split<<<4096, 256>>>((const float4*)W1, (const float4*)W2, (const float4*)W3,
                           (const float4*)x, (float4*)out);
    k_gate<<<T_TOK / 8, 256>>>(x, Wg);
    k_scan<<<1, 1>>>();
    k_assign<<<T_TOK / 256, 256>>>();
    k_ffn1<<<dim3(HID / 64, 32, NEXP), 256, SMEM1>>>();
    k_ffn2<<<dim3(DIM / 64, 32, NEXP), 256, SMEM2>>>(out);
}